// round 12
// baseline (speedup 1.0000x reference)
#include <cuda_runtime.h>
#include <cstdint>
#include <math.h>

#define Bq 2
#define Lq 1024
#define Aq 14
#define Kq 30
#define EFq 128
#define EDGE_INq 3152
#define Mrows (Bq*Lq*Kq)      // 61440
#define BM 128
#define NCHUNK 99             // padded K = 3168

typedef uint32_t u32;

// ---- scratch ----
__device__ int g_Eidx[Mrows];
__device__ __align__(16) float g_X2[Bq*Lq*Aq*3];
__device__ __align__(16) float g_Wfrag[NCHUNK*4096];  // fragment-ordered tf32 W

__constant__ float c_freq[8] = {
    1.0f, 0.31622776601683794f, 0.1f, 0.031622776601683794f,
    0.01f, 0.0031622776601683794f, 0.001f, 0.00031622776601683794f
};

__device__ __forceinline__ u32 f2tf32(float v) {
    u32 u; asm("cvt.rna.tf32.f32 %0, %1;" : "=r"(u) : "f"(v)); return u;
}
__device__ __forceinline__ float ex2f(float x) {
    float r; asm("ex2.approx.f32 %0, %1;" : "=f"(r) : "f"(x)); return r;
}
__device__ __forceinline__ u32 smem_u32(const void* p) {
    u32 a; asm("{ .reg .u64 t; cvta.to.shared.u64 t, %1; cvt.u32.u64 %0, t; }"
               : "=r"(a) : "l"(p));
    return a;
}
__device__ __forceinline__ void mma_tf32(float* d, const u32* a, u32 b0, u32 b1) {
    asm volatile("mma.sync.aligned.m16n8k8.row.col.f32.tf32.tf32.f32 "
        "{%0,%1,%2,%3}, {%4,%5,%6,%7}, {%8,%9}, {%0,%1,%2,%3};"
        : "+f"(d[0]), "+f"(d[1]), "+f"(d[2]), "+f"(d[3])
        : "r"(a[0]), "r"(a[1]), "r"(a[2]), "r"(a[3]), "r"(b0), "r"(b1));
}
#define CP_ASYNC16(dst, src) asm volatile( \
    "cp.async.cg.shared.global [%0], [%1], 16;" :: "r"(dst), "l"(src) : "memory")
#define CP_COMMIT() asm volatile("cp.async.commit_group;" ::: "memory")
#define CP_WAIT1()  asm volatile("cp.async.wait_group 1;" ::: "memory")
#define LDS128(v, addr) asm volatile("ld.shared.v4.f32 {%0,%1,%2,%3}, [%4];" \
    : "=f"(v.x), "=f"(v.y), "=f"(v.z), "=f"(v.w) : "r"(addr))
#define STS128(addr, a0, a1, a2, a3) asm volatile( \
    "st.shared.v4.b32 [%0], {%1,%2,%3,%4};" \
    :: "r"(addr), "r"(a0), "r"(a1), "r"(a2), "r"(a3) : "memory")

// =====================================================================
// Kernel 1 (merged prep): topk | prepW | buildX2
// =====================================================================
#define TOPK_BLOCKS  (Bq*Lq)                 // 2048
#define PREPW_BLOCKS ((NCHUNK*4096)/256)     // 1584
#define BX2_BLOCKS   8
#define PREP_GRID    (TOPK_BLOCKS + PREPW_BLOCKS + BX2_BLOCKS)

__global__ void prep_kernel(const float* __restrict__ X,
                            const float* __restrict__ mask,
                            const float* __restrict__ W,
                            float* __restrict__ out_tail) {
    __shared__ float Da[Lq];
    __shared__ float svals[8];
    __shared__ int   sidx[8];
    __shared__ float sDmax;

    int bid = blockIdx.x;
    int tid = threadIdx.x;

    if (bid >= TOPK_BLOCKS) {
        if (bid < TOPK_BLOCKS + PREPW_BLOCKS) {
            // ---- prepW: per chunk float idx e(0-1)|lane(2-6)|q(7-8)|s(9-10)|wn(11)
            int t = (bid - TOPK_BLOCKS) * 256 + tid;
            int e    = t & 3;
            int lane = (t >> 2) & 31;
            int q    = (t >> 7) & 3;
            int s    = (t >> 9) & 3;
            int wn   = (t >> 11) & 1;
            int k    = t >> 12;
            int nt   = 2*q + (e >> 1);
            int half = e & 1;
            int n = wn*64 + nt*8 + (lane >> 2);
            int c = k*32 + s*8 + (lane & 3) + half*4;
            float v = (c < EDGE_INq) ? W[(size_t)n * EDGE_INq + c] : 0.f;
            g_Wfrag[t] = __uint_as_float(f2tf32(v));
        } else {
            // ---- buildX2 ----
            int t = (bid - TOPK_BLOCKS - PREPW_BLOCKS) * 256 + tid;
            if (t < Bq * Lq) {
                const float* xr = X + (size_t)t * Aq * 3;
                float* o = g_X2 + (size_t)t * Aq * 3;
                #pragma unroll
                for (int a = 0; a < Aq*3; a++) o[a] = xr[a];
                float Nx = xr[0],  Ny = xr[1],  Nz = xr[2];
                float Cax= xr[3],  Cay= xr[4],  Caz= xr[5];
                float Cx = xr[6],  Cy = xr[7],  Cz = xr[8];
                float bx = Cax - Nx, by = Cay - Ny, bz = Caz - Nz;
                float cx = Cx - Cax, cy = Cy - Cay, cz = Cz - Caz;
                float ax = by*cz - bz*cy;
                float ay = bz*cx - bx*cz;
                float az = bx*cy - by*cx;
                o[12] = -0.58273431f*ax + 0.56802827f*bx - 0.54067466f*cx + Cax;
                o[13] = -0.58273431f*ay + 0.56802827f*by - 0.54067466f*cy + Cay;
                o[14] = -0.58273431f*az + 0.56802827f*bz - 0.54067466f*cz + Caz;
            }
        }
        return;
    }

    // ---- topk (unchanged) ----
    int bi  = bid;
    int b   = bi >> 10;
    int i   = bi & (Lq - 1);

    const float* Xb = X + (size_t)b * Lq * Aq * 3;
    float cx = Xb[(i*Aq+1)*3+0];
    float cy = Xb[(i*Aq+1)*3+1];
    float cz = Xb[(i*Aq+1)*3+2];
    float mi = mask[b*Lq + i];

    float lmax = 0.f;
    for (int j = tid; j < Lq; j += 256) {
        float dx = cx - Xb[(j*Aq+1)*3+0];
        float dy = cy - Xb[(j*Aq+1)*3+1];
        float dz = cz - Xb[(j*Aq+1)*3+2];
        float m2 = mi * mask[b*Lq + j];
        float D  = m2 * sqrtf(dx*dx + dy*dy + dz*dz + 1e-6f);
        Da[j] = D;
        lmax = fmaxf(lmax, D);
    }
    #pragma unroll
    for (int off = 16; off; off >>= 1)
        lmax = fmaxf(lmax, __shfl_xor_sync(0xffffffffu, lmax, off));
    if ((tid & 31) == 0) svals[tid >> 5] = lmax;
    __syncthreads();
    if (tid == 0) {
        float m = svals[0];
        for (int w = 1; w < 8; w++) m = fmaxf(m, svals[w]);
        sDmax = m;
    }
    __syncthreads();
    float Dmax = sDmax;
    for (int j = tid; j < Lq; j += 256) {
        float m2 = mi * mask[b*Lq + j];
        Da[j] += 2.f * (1.f - m2) * Dmax;
    }
    __syncthreads();

    for (int k = 0; k < Kq; k++) {
        float bv = 3.4e38f; int bj = 0x7fffffff;
        for (int j = tid; j < Lq; j += 256) {
            float v = Da[j];
            if (v < bv) { bv = v; bj = j; }
        }
        #pragma unroll
        for (int off = 16; off; off >>= 1) {
            float ov = __shfl_down_sync(0xffffffffu, bv, off);
            int   oj = __shfl_down_sync(0xffffffffu, bj, off);
            if (ov < bv || (ov == bv && oj < bj)) { bv = ov; bj = oj; }
        }
        if ((tid & 31) == 0) { svals[tid >> 5] = bv; sidx[tid >> 5] = bj; }
        __syncthreads();
        if (tid == 0) {
            for (int w = 1; w < 8; w++) {
                float v = svals[w]; int jj = sidx[w];
                if (v < bv || (v == bv && jj < bj)) { bv = v; bj = jj; }
            }
            int orow = bi * Kq + k;
            g_Eidx[orow] = bj;
            if (out_tail) out_tail[orow] = (float)bj;
            Da[bj] = 3.4e38f;
        }
        __syncthreads();
    }
}

// =====================================================================
// Kernel 2: fused featuregen + mma.sync tf32 + LayerNorm
// 1-barrier/chunk pipeline: consume(k) || stage(k+2) || produce(k+1).
// afr x2, B ring x4, sD ring x4, all literal indices (period-4 unroll).
// =====================================================================
// byte offsets in dynamic smem
#define SM_SBF   0          // 4 * 16384 = 65536 (B quad buffer)
#define SM_SD    65536      // 4 rings * 256 f = 4096
#define SM_SCO   69632      // 4096
#define SM_DPOS  73728      // 512
#define SM_IIDX  74240      // 512
#define SM_JIDX  74752      // 512
#define SM_AFR   75264      // 2 bufs * 16384 = 32768
#define SM_TOTAL 108032
#define ESTRIDE  132        // epilogue reuses bytes [0, 33792)

// ---------- stage sD(k+2) into ring SDR + issue B(k+2) into buffer NB ----
#define STAGE_NEXT(SDR, NB) do {                                             \
    float D = 0.f, co = 0.f;                                                 \
    if (sp < 14) {                                                           \
        const float* xi = xi_b + sp*3;                                       \
        const float* xj = xj_b + sq*3;                                       \
        float dx = xi[0]-xj[0], dy = xi[1]-xj[1], dz = xi[2]-xj[2];          \
        D  = sqrtf(dx*dx + dy*dy + dz*dz + 1e-6f);                          \
        co = (1.f - ami_b[sp]) * (1.f - amj_b[sq]);                          \
    }                                                                        \
    sDf [(SDR)*256 + st_off] = D;                                            \
    sCof[(SDR)*256 + st_off] = co;                                           \
    sq += 2; if (sq >= 14) { sq -= 14; sp += 1; }                            \
    CP_ASYNC16(bdst + (NB)*16384 +     0, wsrc_n      );                     \
    CP_ASYNC16(bdst + (NB)*16384 +  4096, wsrc_n + 256);                     \
    CP_ASYNC16(bdst + (NB)*16384 +  8192, wsrc_n + 512);                     \
    CP_ASYNC16(bdst + (NB)*16384 + 12288, wsrc_n + 768);                     \
    wsrc_n += 1024;                                                          \
} while(0)

// ---------- produce rbf fragments from sD ring SDR into afr buffer AB ----
#define PRODUCE_RBF(SDR, AB) do {                                            \
    _Pragma("unroll")                                                        \
    for (int sp2 = 0; sp2 < 2; sp2++) {                                      \
        float m0 = sp2 ? mu10 : mu00;                                        \
        float m1 = sp2 ? mu11 : mu01;                                        \
        _Pragma("unroll")                                                    \
        for (int mt = 0; mt < 2; mt++) {                                     \
            int ri = (SDR)*256 + sd_rd + (mt<<4);                            \
            float D0 = sDf[ri],     C0 = sCof[ri];                           \
            float D1 = sDf[ri + 8], C1 = sCof[ri + 8];                       \
            float t0 = D0 - m0, t1 = D1 - m0;                                \
            float t2 = D0 - m1, t3 = D1 - m1;                                \
            u32 v0 = f2tf32(C0 * ex2f(t0*t0*-0.9233248262f));                \
            u32 v1 = f2tf32(C1 * ex2f(t1*t1*-0.9233248262f));                \
            u32 v2 = f2tf32(C0 * ex2f(t2*t2*-0.9233248262f));                \
            u32 v3 = f2tf32(C1 * ex2f(t3*t3*-0.9233248262f));                \
            STS128(afr_st + (u32)((AB)*16384 + sp2*1024 + mt*512),           \
                   v0, v1, v2, v3);                                          \
        }                                                                    \
    }                                                                        \
} while(0)

// ---------- consume chunk: afr buffer AB + B buffer BB ----
#define CONSUME(BB, AB) do {                                                 \
    _Pragma("unroll")                                                        \
    for (int s = 0; s < 4; s++) {                                            \
        u32 afr[2][4];                                                       \
        _Pragma("unroll")                                                    \
        for (int mt = 0; mt < 2; mt++) {                                     \
            float4 av;                                                       \
            LDS128(av, abase + (u32)((AB)*16384 + (((s<<1)+mt)<<9)));        \
            afr[mt][0] = __float_as_uint(av.x);                              \
            afr[mt][1] = __float_as_uint(av.y);                              \
            afr[mt][2] = __float_as_uint(av.z);                              \
            afr[mt][3] = __float_as_uint(av.w);                              \
        }                                                                    \
        _Pragma("unroll")                                                    \
        for (int q = 0; q < 4; q++) {                                        \
            float4 bv;                                                       \
            LDS128(bv, sbase + (u32)((BB)*16384 + (s<<11) + (q<<9)));        \
            u32 b0 = __float_as_uint(bv.x), b1 = __float_as_uint(bv.y);      \
            u32 b2 = __float_as_uint(bv.z), b3 = __float_as_uint(bv.w);      \
            _Pragma("unroll")                                                \
            for (int mt = 0; mt < 2; mt++) {                                 \
                mma_tf32(acc[mt][2*q],     afr[mt], b0, b1);                 \
                mma_tf32(acc[mt][2*q + 1], afr[mt], b2, b3);                 \
            }                                                                \
        }                                                                    \
    }                                                                        \
} while(0)

// ---------- one pipelined chunk (k): BB=k%4 AB=k%2; stage k+2; produce k+1
#define CHUNK_P(BB, AB, SDN, SDP, ABN, HAS_STAGE, HAS_PROD) do {             \
    __syncthreads();                                                         \
    CONSUME(BB, AB);                                                         \
    if (HAS_STAGE) STAGE_NEXT(SDN, SDN);                                     \
    CP_COMMIT();                                                             \
    if (HAS_PROD) PRODUCE_RBF(SDP, ABN);                                     \
    CP_WAIT1();                                                              \
} while(0)

__global__ void __launch_bounds__(256, 2)
fused_hmma_kernel(const float* __restrict__ atom_mask,
                  const float* __restrict__ gamma_,
                  const float* __restrict__ beta_,
                  float* __restrict__ out) {
    extern __shared__ char smc[];
    u32 sb = smem_u32(smc);
    float* sE    = (float*)(smc);               // epilogue reuse
    float* sDf   = (float*)(smc + SM_SD);
    float* sCof  = (float*)(smc + SM_SCO);
    float* dposS = (float*)(smc + SM_DPOS);
    int*   iidx  = (int*)(smc + SM_IIDX);
    int*   jidx  = (int*)(smc + SM_JIDX);

    int tid  = threadIdx.x;
    int wid  = tid >> 5, lane = tid & 31;
    int wm   = wid & 3, wn = wid >> 2;
    int lq   = lane >> 2;    // 0..7
    int lr   = lane & 3;     // 0..3
    int row0 = blockIdx.x * BM;

    if (tid < BM) {
        int gr  = row0 + tid;
        int b   = gr / (Lq * Kq);
        int rem = gr - b * (Lq * Kq);
        int i   = rem / Kq;
        int j   = g_Eidx[gr];
        iidx[tid] = b * Lq + i;
        jidx[tid] = b * Lq + j;
        dposS[tid] = (float)(j - i);
    }
    __syncthreads();

    // ---- hoisted per-thread staging state ----
    int srow = tid & 127;
    int sl   = tid >> 7;
    const float* xi_b  = g_X2 + iidx[srow]*42;
    const float* xj_b  = g_X2 + jidx[srow]*42;
    const float* ami_b = atom_mask + iidx[srow]*14;
    const float* amj_b = atom_mask + jidx[srow]*14;
    int sp = 0, sq = 1 + sl;
    int st_off = (sl << 7) + srow;

    // ---- prologue stage sD(0) into ring 0 (P = -1+sl) ----
    {
        float D = 0.f, co = 0.f;
        if (sl == 1) {
            float dx = xi_b[0]-xj_b[0], dy = xi_b[1]-xj_b[1], dz = xi_b[2]-xj_b[2];
            D  = sqrtf(dx*dx + dy*dy + dz*dz + 1e-6f);
            co = (1.f - ami_b[0]) * (1.f - amj_b[0]);
        }
        sDf [st_off] = D;
        sCof[st_off] = co;
    }
    // ---- prologue stage sD(1) into ring 1 (P = 1+sl) ----
    {
        float D = 0.f, co = 0.f;
        {
            const float* xi = xi_b + sp*3;
            const float* xj = xj_b + sq*3;
            float dx = xi[0]-xj[0], dy = xi[1]-xj[1], dz = xi[2]-xj[2];
            D  = sqrtf(dx*dx + dy*dy + dz*dz + 1e-6f);
            co = (1.f - ami_b[sp]) * (1.f - amj_b[sq]);
        }
        sDf [256 + st_off] = D;
        sCof[256 + st_off] = co;
        sq += 2; if (sq >= 14) { sq -= 14; sp += 1; }
    }
    // ---- prologue B(0), B(1) ----
    u32 bdst = sb + SM_SBF + (u32)(tid << 4);
    const float4* wsrc_n = (const float4*)g_Wfrag + tid;
    CP_ASYNC16(bdst +     0, wsrc_n      );
    CP_ASYNC16(bdst +  4096, wsrc_n + 256);
    CP_ASYNC16(bdst +  8192, wsrc_n + 512);
    CP_ASYNC16(bdst + 12288, wsrc_n + 768);
    CP_COMMIT();
    wsrc_n += 1024;
    CP_ASYNC16(bdst + 16384 +     0, wsrc_n      );
    CP_ASYNC16(bdst + 16384 +  4096, wsrc_n + 256);
    CP_ASYNC16(bdst + 16384 +  8192, wsrc_n + 512);
    CP_ASYNC16(bdst + 16384 + 12288, wsrc_n + 768);
    CP_COMMIT();
    wsrc_n += 1024;

    // ---- hoisted producer/consumer bases ----
    int sd_rd   = (wn << 7) + (wm << 5) + lq;
    u32 afr_st  = sb + SM_AFR + (u32)((wm << 12) + (wn << 11) + (lane << 4));
    u32 abase   = sb + SM_AFR + (u32)((wm << 12) + (lane << 4));
    u32 sbase   = sb + SM_SBF + (u32)((wn << 13) + (lane << 4));
    float mu00 = (float)lr * 1.3333333333f;
    float mu01 = mu00 + 5.3333333333f;
    float mu10 = (float)(8 + lr) * 1.3333333333f;
    float mu11 = mu10 + 5.3333333333f;

    __syncthreads();       // publish sD rings 0,1

    // ---- prologue produce(0) -> afr buf 0 ----
    if (wn == 0) {
        // posenc: sp2=0 cos, sp2=1 sin
        #pragma unroll
        for (int sp2 = 0; sp2 < 2; sp2++) {
            #pragma unroll
            for (int mt = 0; mt < 2; mt++) {
                int r0 = (wm << 5) + (mt << 4) + lq;
                float d0 = dposS[r0], d1 = dposS[r0 + 8];
                float s0a, c0a, s1a, c1a, s0b, c0b, s1b, c1b;
                sincosf(d0 * c_freq[lr],     &s0a, &c0a);
                sincosf(d1 * c_freq[lr],     &s1a, &c1a);
                sincosf(d0 * c_freq[lr + 4], &s0b, &c0b);
                sincosf(d1 * c_freq[lr + 4], &s1b, &c1b);
                u32 v0, v1, v2, v3;
                if (sp2 == 0) {
                    v0 = f2tf32(c0a); v1 = f2tf32(c1a);
                    v2 = f2tf32(c0b); v3 = f2tf32(c1b);
                } else {
                    v0 = f2tf32(s0a); v1 = f2tf32(s1a);
                    v2 = f2tf32(s0b); v3 = f2tf32(s1b);
                }
                STS128(afr_st + (u32)(sp2*1024 + mt*512), v0, v1, v2, v3);
            }
        }
    } else {
        PRODUCE_RBF(0, 0);     // rbf pair P=0 (sD ring 0), s=2,3
    }
    CP_WAIT1();                // B(0) complete

    float acc[2][8][4];
    #pragma unroll
    for (int mt = 0; mt < 2; mt++)
        #pragma unroll
        for (int nt = 0; nt < 8; nt++)
            #pragma unroll
            for (int c = 0; c < 4; c++) acc[mt][nt][c] = 0.f;

    // ================= chunks 0..95 : 24 x 4 unrolled =================
    #pragma unroll 1
    for (int kb = 0; kb < 24; kb++) {
        CHUNK_P(0, 0, 2, 1, 1, 1, 1);   // k = 4kb+0
        CHUNK_P(1, 1, 3, 2, 0, 1, 1);   // k = 4kb+1
        CHUNK_P(2, 0, 0, 3, 1, 1, 1);   // k = 4kb+2
        CHUNK_P(3, 1, 1, 0, 0, 1, 1);   // k = 4kb+3
    }
    // ================= chunks 96, 97, 98 =================
    CHUNK_P(0, 0, 2, 1, 1, 1, 1);       // k=96: stage 98, produce 97
    CHUNK_P(1, 1, 3, 2, 0, 0, 1);       // k=97: produce 98 only
    CHUNK_P(2, 0, 0, 3, 1, 0, 0);       // k=98: consume only

    // ================= epilogue: 2 halves of 64 rows =================
    float4 g4 = *(const float4*)&gamma_[lane << 2];
    float4 b4 = *(const float4*)&beta_ [lane << 2];

    #pragma unroll
    for (int h = 0; h < 2; h++) {
        __syncthreads();
        if ((wm >> 1) == h) {
            #pragma unroll
            for (int mt = 0; mt < 2; mt++) {
                int rl = (wm << 5) + (mt << 4) + lq - (h << 6);
                #pragma unroll
                for (int nt = 0; nt < 8; nt++) {
                    int col = (wn << 6) + (nt << 3) + (lr << 1);
                    *(float2*)&sE[ rl      * ESTRIDE + col] =
                        make_float2(acc[mt][nt][0], acc[mt][nt][1]);
                    *(float2*)&sE[(rl + 8) * ESTRIDE + col] =
                        make_float2(acc[mt][nt][2], acc[mt][nt][3]);
                }
            }
        }
        __syncthreads();
        #pragma unroll
        for (int rr = 0; rr < 8; rr++) {
            int rl = (wid << 3) + rr;
            float4 v = *(const float4*)&sE[rl * ESTRIDE + (lane << 2)];
            float s  = v.x + v.y + v.z + v.w;
            float sq2 = v.x*v.x + v.y*v.y + v.z*v.z + v.w*v.w;
            #pragma unroll
            for (int off = 16; off; off >>= 1) {
                s   += __shfl_xor_sync(0xffffffffu, s,   off);
                sq2 += __shfl_xor_sync(0xffffffffu, sq2, off);
            }
            float mean = s * (1.f/128.f);
            float var  = sq2 * (1.f/128.f) - mean * mean;
            float inv  = rsqrtf(var + 1e-5f);
            int gr = row0 + (h << 6) + rl;
            float4 o;
            o.x = (v.x - mean)*inv*g4.x + b4.x;
            o.y = (v.y - mean)*inv*g4.y + b4.y;
            o.z = (v.z - mean)*inv*g4.z + b4.z;
            o.w = (v.w - mean)*inv*g4.w + b4.w;
            *(float4*)&out[(size_t)gr * EFq + (lane << 2)] = o;
        }
    }
}

// =====================================================================
extern "C" void kernel_launch(void* const* d_in, const int* in_sizes, int n_in,
                              void* d_out, int out_size) {
    const float* X         = (const float*)d_in[0];
    const float* mask      = (const float*)d_in[1];
    const float* atom_mask = (const float*)d_in[4];
    const float* W         = (const float*)d_in[5];
    const float* gamma_    = (const float*)d_in[6];
    const float* beta_     = (const float*)d_in[7];
    float* out = (float*)d_out;

    float* out_tail = (out_size >= Mrows * (EFq + 1)) ? (out + (size_t)Mrows * EFq)
                                                      : nullptr;

    prep_kernel<<<PREP_GRID, 256>>>(X, mask, W, out_tail);

    cudaFuncSetAttribute(fused_hmma_kernel,
                         cudaFuncAttributeMaxDynamicSharedMemorySize, SM_TOTAL);
    fused_hmma_kernel<<<Mrows/BM, 256, SM_TOTAL>>>(atom_mask, gamma_, beta_, out);
}

// round 13
// speedup vs baseline: 1.0151x; 1.0151x over previous
#include <cuda_runtime.h>
#include <cstdint>
#include <math.h>

#define Bq 2
#define Lq 1024
#define Aq 14
#define Kq 30
#define EFq 128
#define EDGE_INq 3152
#define Mrows (Bq*Lq*Kq)      // 61440
#define BM 128
#define NCHUNK 99             // padded K = 3168

typedef uint32_t u32;

// ---- scratch ----
__device__ int g_Eidx[Mrows];
__device__ __align__(16) float g_X2[Bq*Lq*Aq*3];
__device__ __align__(16) float g_Wfrag[NCHUNK*4096];  // fragment-ordered tf32 W

__constant__ float c_freq[8] = {
    1.0f, 0.31622776601683794f, 0.1f, 0.031622776601683794f,
    0.01f, 0.0031622776601683794f, 0.001f, 0.00031622776601683794f
};

__device__ __forceinline__ u32 f2tf32(float v) {
    u32 u; asm("cvt.rna.tf32.f32 %0, %1;" : "=r"(u) : "f"(v)); return u;
}
__device__ __forceinline__ float ex2f(float x) {
    float r; asm("ex2.approx.f32 %0, %1;" : "=f"(r) : "f"(x)); return r;
}
__device__ __forceinline__ u32 smem_u32(const void* p) {
    u32 a; asm("{ .reg .u64 t; cvta.to.shared.u64 t, %1; cvt.u32.u64 %0, t; }"
               : "=r"(a) : "l"(p));
    return a;
}
__device__ __forceinline__ void mma_tf32(float* d, const u32* a, u32 b0, u32 b1) {
    asm volatile("mma.sync.aligned.m16n8k8.row.col.f32.tf32.tf32.f32 "
        "{%0,%1,%2,%3}, {%4,%5,%6,%7}, {%8,%9}, {%0,%1,%2,%3};"
        : "+f"(d[0]), "+f"(d[1]), "+f"(d[2]), "+f"(d[3])
        : "r"(a[0]), "r"(a[1]), "r"(a[2]), "r"(a[3]), "r"(b0), "r"(b1));
}
#define CP_ASYNC16(dst, src) asm volatile( \
    "cp.async.cg.shared.global [%0], [%1], 16;" :: "r"(dst), "l"(src) : "memory")
#define CP_COMMIT() asm volatile("cp.async.commit_group;" ::: "memory")
#define CP_WAIT1()  asm volatile("cp.async.wait_group 1;" ::: "memory")
#define LDS128(v, addr) asm volatile("ld.shared.v4.f32 {%0,%1,%2,%3}, [%4];" \
    : "=f"(v.x), "=f"(v.y), "=f"(v.z), "=f"(v.w) : "r"(addr))
#define STS128(addr, a0, a1, a2, a3) asm volatile( \
    "st.shared.v4.b32 [%0], {%1,%2,%3,%4};" \
    :: "r"(addr), "r"(a0), "r"(a1), "r"(a2), "r"(a3) : "memory")

// =====================================================================
// Kernel 1 (merged prep): topk | prepW | buildX2
// =====================================================================
#define TOPK_BLOCKS  (Bq*Lq)                 // 2048
#define PREPW_BLOCKS ((NCHUNK*4096)/256)     // 1584
#define BX2_BLOCKS   8
#define PREP_GRID    (TOPK_BLOCKS + PREPW_BLOCKS + BX2_BLOCKS)

__global__ void prep_kernel(const float* __restrict__ X,
                            const float* __restrict__ mask,
                            const float* __restrict__ W,
                            float* __restrict__ out_tail) {
    __shared__ float Da[Lq];
    __shared__ float svals[8];
    __shared__ int   sidx[8];
    __shared__ float sDmax;

    int bid = blockIdx.x;
    int tid = threadIdx.x;

    if (bid >= TOPK_BLOCKS) {
        if (bid < TOPK_BLOCKS + PREPW_BLOCKS) {
            // ---- prepW: per chunk float idx e(0-1)|lane(2-6)|q(7-8)|s(9-10)|wn(11)
            int t = (bid - TOPK_BLOCKS) * 256 + tid;
            int e    = t & 3;
            int lane = (t >> 2) & 31;
            int q    = (t >> 7) & 3;
            int s    = (t >> 9) & 3;
            int wn   = (t >> 11) & 1;
            int k    = t >> 12;
            int nt   = 2*q + (e >> 1);
            int half = e & 1;
            int n = wn*64 + nt*8 + (lane >> 2);
            int c = k*32 + s*8 + (lane & 3) + half*4;
            float v = (c < EDGE_INq) ? W[(size_t)n * EDGE_INq + c] : 0.f;
            g_Wfrag[t] = __uint_as_float(f2tf32(v));
        } else {
            // ---- buildX2 ----
            int t = (bid - TOPK_BLOCKS - PREPW_BLOCKS) * 256 + tid;
            if (t < Bq * Lq) {
                const float* xr = X + (size_t)t * Aq * 3;
                float* o = g_X2 + (size_t)t * Aq * 3;
                #pragma unroll
                for (int a = 0; a < Aq*3; a++) o[a] = xr[a];
                float Nx = xr[0],  Ny = xr[1],  Nz = xr[2];
                float Cax= xr[3],  Cay= xr[4],  Caz= xr[5];
                float Cx = xr[6],  Cy = xr[7],  Cz = xr[8];
                float bx = Cax - Nx, by = Cay - Ny, bz = Caz - Nz;
                float cx = Cx - Cax, cy = Cy - Cay, cz = Cz - Caz;
                float ax = by*cz - bz*cy;
                float ay = bz*cx - bx*cz;
                float az = bx*cy - by*cx;
                o[12] = -0.58273431f*ax + 0.56802827f*bx - 0.54067466f*cx + Cax;
                o[13] = -0.58273431f*ay + 0.56802827f*by - 0.54067466f*cy + Cay;
                o[14] = -0.58273431f*az + 0.56802827f*bz - 0.54067466f*cz + Caz;
            }
        }
        return;
    }

    // ---- topk (unchanged) ----
    int bi  = bid;
    int b   = bi >> 10;
    int i   = bi & (Lq - 1);

    const float* Xb = X + (size_t)b * Lq * Aq * 3;
    float cx = Xb[(i*Aq+1)*3+0];
    float cy = Xb[(i*Aq+1)*3+1];
    float cz = Xb[(i*Aq+1)*3+2];
    float mi = mask[b*Lq + i];

    float lmax = 0.f;
    for (int j = tid; j < Lq; j += 256) {
        float dx = cx - Xb[(j*Aq+1)*3+0];
        float dy = cy - Xb[(j*Aq+1)*3+1];
        float dz = cz - Xb[(j*Aq+1)*3+2];
        float m2 = mi * mask[b*Lq + j];
        float D  = m2 * sqrtf(dx*dx + dy*dy + dz*dz + 1e-6f);
        Da[j] = D;
        lmax = fmaxf(lmax, D);
    }
    #pragma unroll
    for (int off = 16; off; off >>= 1)
        lmax = fmaxf(lmax, __shfl_xor_sync(0xffffffffu, lmax, off));
    if ((tid & 31) == 0) svals[tid >> 5] = lmax;
    __syncthreads();
    if (tid == 0) {
        float m = svals[0];
        for (int w = 1; w < 8; w++) m = fmaxf(m, svals[w]);
        sDmax = m;
    }
    __syncthreads();
    float Dmax = sDmax;
    for (int j = tid; j < Lq; j += 256) {
        float m2 = mi * mask[b*Lq + j];
        Da[j] += 2.f * (1.f - m2) * Dmax;
    }
    __syncthreads();

    for (int k = 0; k < Kq; k++) {
        float bv = 3.4e38f; int bj = 0x7fffffff;
        for (int j = tid; j < Lq; j += 256) {
            float v = Da[j];
            if (v < bv) { bv = v; bj = j; }
        }
        #pragma unroll
        for (int off = 16; off; off >>= 1) {
            float ov = __shfl_down_sync(0xffffffffu, bv, off);
            int   oj = __shfl_down_sync(0xffffffffu, bj, off);
            if (ov < bv || (ov == bv && oj < bj)) { bv = ov; bj = oj; }
        }
        if ((tid & 31) == 0) { svals[tid >> 5] = bv; sidx[tid >> 5] = bj; }
        __syncthreads();
        if (tid == 0) {
            for (int w = 1; w < 8; w++) {
                float v = svals[w]; int jj = sidx[w];
                if (v < bv || (v == bv && jj < bj)) { bv = v; bj = jj; }
            }
            int orow = bi * Kq + k;
            g_Eidx[orow] = bj;
            if (out_tail) out_tail[orow] = (float)bj;
            Da[bj] = 3.4e38f;
        }
        __syncthreads();
    }
}

// =====================================================================
// Kernel 2: fused featuregen + mma.sync tf32 + LayerNorm
// 512 threads, 16 warps = wm(4) x wn(4); acc[2][4][4]=32 regs -> 2 CTA/SM
// R11 schedule: stage(k+1); commit; wait1; sync; produce(k); sync; consume(k)
// =====================================================================
// byte offsets in dynamic smem
#define SM_SBF   0          // 3 * 16384 = 49152 (B triple buffer)
#define SM_SD    49152      // 2 bufs * 256 f = 2048
#define SM_SCO   51200      // 2048
#define SM_DPOS  53248      // 512
#define SM_IIDX  53760      // 512
#define SM_JIDX  54272      // 512
#define SM_AFR   54784      // 4 wm x 4 s x 2 mt x 512B = 16384
#define SM_TOTAL 71168
#define ESTRIDE  132        // epilogue reuses bytes [0, 33792)

// ---------- stage sD(k+1) into buf SDW + issue B(k+1) into buffer NB ----
#define STAGE_NEXT(SDW, NB) do {                                             \
    if (tid < 256) {                                                         \
        float D = 0.f, co = 0.f;                                             \
        if (sp < 14) {                                                       \
            const float* xi = g_X2 + iis*42 + sp*3;                          \
            const float* xj = g_X2 + jjs*42 + sq*3;                          \
            float dx = xi[0]-xj[0], dy = xi[1]-xj[1], dz = xi[2]-xj[2];      \
            D  = sqrtf(dx*dx + dy*dy + dz*dz + 1e-6f);                      \
            co = (1.f - atom_mask[iis*14 + sp]) *                            \
                 (1.f - atom_mask[jjs*14 + sq]);                             \
        }                                                                    \
        sDf [(SDW)*256 + st_off] = D;                                        \
        sCof[(SDW)*256 + st_off] = co;                                       \
        sq += 2; if (sq >= 14) { sq -= 14; sp += 1; }                        \
    }                                                                        \
    CP_ASYNC16(bdst + (NB)*16384,        wsrc_n      );                      \
    CP_ASYNC16(bdst + (NB)*16384 + 8192, wsrc_n + 512);                      \
    wsrc_n += 1024;                                                          \
} while(0)

// ---------- produce: warp (wm,wn) makes s=wn fragments for its wm ----
#define PRODUCE_RBF(SDB) do {                                                \
    float m0 = (float)(((wn & 1) << 3) + lr) * 1.3333333333f;                \
    float m1 = m0 + 5.3333333333f;                                           \
    _Pragma("unroll")                                                        \
    for (int mt = 0; mt < 2; mt++) {                                         \
        int ri = (SDB)*256 + sd_rd + (mt<<4);                                \
        float D0 = sDf[ri],     C0 = sCof[ri];                               \
        float D1 = sDf[ri + 8], C1 = sCof[ri + 8];                           \
        float t0 = D0 - m0, t1 = D1 - m0;                                    \
        float t2 = D0 - m1, t3 = D1 - m1;                                    \
        u32 v0 = f2tf32(C0 * ex2f(t0*t0*-0.9233248262f));                    \
        u32 v1 = f2tf32(C1 * ex2f(t1*t1*-0.9233248262f));                    \
        u32 v2 = f2tf32(C0 * ex2f(t2*t2*-0.9233248262f));                    \
        u32 v3 = f2tf32(C1 * ex2f(t3*t3*-0.9233248262f));                    \
        STS128(afr_st + (u32)(mt*512), v0, v1, v2, v3);                      \
    }                                                                        \
} while(0)

// ---------- consume chunk: B buffer BB ----
#define CONSUME(BB) do {                                                     \
    _Pragma("unroll")                                                        \
    for (int s = 0; s < 4; s++) {                                            \
        u32 afr[2][4];                                                       \
        _Pragma("unroll")                                                    \
        for (int mt = 0; mt < 2; mt++) {                                     \
            float4 av;                                                       \
            LDS128(av, abase + (u32)((s<<10) + (mt<<9)));                    \
            afr[mt][0] = __float_as_uint(av.x);                              \
            afr[mt][1] = __float_as_uint(av.y);                              \
            afr[mt][2] = __float_as_uint(av.z);                              \
            afr[mt][3] = __float_as_uint(av.w);                              \
        }                                                                    \
        _Pragma("unroll")                                                    \
        for (int q = 0; q < 2; q++) {                                        \
            float4 bv;                                                       \
            LDS128(bv, sbase + (u32)((BB)*16384 + (s<<11) + (q<<9)));        \
            u32 b0 = __float_as_uint(bv.x), b1 = __float_as_uint(bv.y);      \
            u32 b2 = __float_as_uint(bv.z), b3 = __float_as_uint(bv.w);      \
            _Pragma("unroll")                                                \
            for (int mt = 0; mt < 2; mt++) {                                 \
                mma_tf32(acc[mt][2*q],     afr[mt], b0, b1);                 \
                mma_tf32(acc[mt][2*q + 1], afr[mt], b2, b3);                 \
            }                                                                \
        }                                                                    \
    }                                                                        \
} while(0)

#define CHUNK_STD(SDB, BB, NB, HAS_NEXT) do {                                \
    if (HAS_NEXT) STAGE_NEXT(1-(SDB), NB);                                   \
    CP_COMMIT(); CP_WAIT1(); __syncthreads();                                \
    PRODUCE_RBF(SDB);                                                        \
    __syncthreads();                                                         \
    CONSUME(BB);                                                             \
} while(0)

__global__ void __launch_bounds__(512, 2)
fused_hmma_kernel(const float* __restrict__ atom_mask,
                  const float* __restrict__ gamma_,
                  const float* __restrict__ beta_,
                  float* __restrict__ out) {
    extern __shared__ char smc[];
    u32 sb = smem_u32(smc);
    float* sE    = (float*)(smc);               // epilogue reuse
    float* sDf   = (float*)(smc + SM_SD);
    float* sCof  = (float*)(smc + SM_SCO);
    float* dposS = (float*)(smc + SM_DPOS);
    int*   iidx  = (int*)(smc + SM_IIDX);
    int*   jidx  = (int*)(smc + SM_JIDX);

    int tid  = threadIdx.x;
    int wid  = tid >> 5, lane = tid & 31;
    int wm   = wid & 3, wn = wid >> 2;          // wm 0..3 rows, wn 0..3 cols
    int lq   = lane >> 2;    // 0..7
    int lr   = lane & 3;     // 0..3
    int row0 = blockIdx.x * BM;

    if (tid < BM) {
        int gr  = row0 + tid;
        int b   = gr / (Lq * Kq);
        int rem = gr - b * (Lq * Kq);
        int i   = rem / Kq;
        int j   = g_Eidx[gr];
        iidx[tid] = b * Lq + i;
        jidx[tid] = b * Lq + j;
        dposS[tid] = (float)(j - i);
    }
    __syncthreads();

    // ---- staging state (threads 0..255 only use it) ----
    int srow = tid & 127;
    int sl   = (tid >> 7) & 1;
    int iis = iidx[srow], jjs = jidx[srow];
    int sp = 0, sq = 1 + sl;
    int st_off = (sl << 7) + srow;

    // ---- prologue stage sD(0) into buf 0 (P = -1+sl) ----
    if (tid < 256) {
        float D = 0.f, co = 0.f;
        if (sl == 1) {
            const float* xi = g_X2 + iis*42;
            const float* xj = g_X2 + jjs*42;
            float dx = xi[0]-xj[0], dy = xi[1]-xj[1], dz = xi[2]-xj[2];
            D  = sqrtf(dx*dx + dy*dy + dz*dz + 1e-6f);
            co = (1.f - atom_mask[iis*14]) * (1.f - atom_mask[jjs*14]);
        }
        sDf [st_off] = D;
        sCof[st_off] = co;
    }
    // ---- B(0) prefetch (512 threads x 2 x 16B = 16KB) ----
    u32 bdst = sb + SM_SBF + (u32)(tid << 4);
    const float4* wsrc_n = (const float4*)g_Wfrag + tid;
    CP_ASYNC16(bdst,        wsrc_n      );
    CP_ASYNC16(bdst + 8192, wsrc_n + 512);
    CP_COMMIT();
    wsrc_n += 1024;

    // ---- hoisted bases ----
    int sd_rd   = ((wn >> 1) << 7) + (wm << 5) + lq;
    u32 afr_st  = sb + SM_AFR + (u32)((wm << 12) + (wn << 10) + (lane << 4));
    u32 abase   = sb + SM_AFR + (u32)((wm << 12) + (lane << 4));
    u32 sbase   = sb + SM_SBF + (u32)(((wn >> 1) << 13) + ((wn & 1) << 10) + (lane << 4));

    float acc[2][4][4];
    #pragma unroll
    for (int mt = 0; mt < 2; mt++)
        #pragma unroll
        for (int nt = 0; nt < 4; nt++)
            #pragma unroll
            for (int c = 0; c < 4; c++) acc[mt][nt][c] = 0.f;

    // ================= chunk 0 (posenc for wn 0,1; rbf P=0 for wn 2,3) ====
    {
        STAGE_NEXT(1, 1);
        CP_COMMIT(); CP_WAIT1(); __syncthreads();
        if (wn < 2) {
            #pragma unroll
            for (int mt = 0; mt < 2; mt++) {
                int r0 = (wm << 5) + (mt << 4) + lq;
                float d0 = dposS[r0], d1 = dposS[r0 + 8];
                float s0a, c0a, s1a, c1a, s0b, c0b, s1b, c1b;
                sincosf(d0 * c_freq[lr],     &s0a, &c0a);
                sincosf(d1 * c_freq[lr],     &s1a, &c1a);
                sincosf(d0 * c_freq[lr + 4], &s0b, &c0b);
                sincosf(d1 * c_freq[lr + 4], &s1b, &c1b);
                u32 v0, v1, v2, v3;
                if (wn == 0) {       // s=0: cos
                    v0 = f2tf32(c0a); v1 = f2tf32(c1a);
                    v2 = f2tf32(c0b); v3 = f2tf32(c1b);
                } else {             // s=1: sin
                    v0 = f2tf32(s0a); v1 = f2tf32(s1a);
                    v2 = f2tf32(s0b); v3 = f2tf32(s1b);
                }
                STS128(afr_st + (u32)(mt*512), v0, v1, v2, v3);
            }
        } else {
            PRODUCE_RBF(0);
        }
        __syncthreads();
        CONSUME(0);
    }

    // ================= chunks 1..96 : 16 x 6 unrolled =================
    #pragma unroll 1
    for (int kb = 0; kb < 16; kb++) {
        CHUNK_STD(1, 1, 2, 1);   // k = 6kb+1
        CHUNK_STD(0, 2, 0, 1);   // k = 6kb+2
        CHUNK_STD(1, 0, 1, 1);   // k = 6kb+3
        CHUNK_STD(0, 1, 2, 1);   // k = 6kb+4
        CHUNK_STD(1, 2, 0, 1);   // k = 6kb+5
        CHUNK_STD(0, 0, 1, 1);   // k = 6kb+6
    }
    // ================= chunks 97, 98 =================
    CHUNK_STD(1, 1, 2, 1);       // k = 97 (stages 98; sp<14 guards bounds)
    CHUNK_STD(0, 2, 0, 0);       // k = 98 (no next)

    // ================= epilogue: 2 halves of 64 rows =================
    float4 g4 = *(const float4*)&gamma_[lane << 2];
    float4 b4 = *(const float4*)&beta_ [lane << 2];

    #pragma unroll
    for (int h = 0; h < 2; h++) {
        __syncthreads();
        if ((wm >> 1) == h) {
            #pragma unroll
            for (int mt = 0; mt < 2; mt++) {
                int rl = ((wm & 1) << 5) + (mt << 4) + lq;
                #pragma unroll
                for (int nt = 0; nt < 4; nt++) {
                    int col = (wn << 5) + (nt << 3) + (lr << 1);
                    *(float2*)&sE[ rl      * ESTRIDE + col] =
                        make_float2(acc[mt][nt][0], acc[mt][nt][1]);
                    *(float2*)&sE[(rl + 8) * ESTRIDE + col] =
                        make_float2(acc[mt][nt][2], acc[mt][nt][3]);
                }
            }
        }
        __syncthreads();
        #pragma unroll
        for (int rr = 0; rr < 4; rr++) {
            int rl = (wid << 2) + rr;
            float4 v = *(const float4*)&sE[rl * ESTRIDE + (lane << 2)];
            float s  = v.x + v.y + v.z + v.w;
            float sq2 = v.x*v.x + v.y*v.y + v.z*v.z + v.w*v.w;
            #pragma unroll
            for (int off = 16; off; off >>= 1) {
                s   += __shfl_xor_sync(0xffffffffu, s,   off);
                sq2 += __shfl_xor_sync(0xffffffffu, sq2, off);
            }
            float mean = s * (1.f/128.f);
            float var  = sq2 * (1.f/128.f) - mean * mean;
            float inv  = rsqrtf(var + 1e-5f);
            int gr = row0 + (h << 6) + rl;
            float4 o;
            o.x = (v.x - mean)*inv*g4.x + b4.x;
            o.y = (v.y - mean)*inv*g4.y + b4.y;
            o.z = (v.z - mean)*inv*g4.z + b4.z;
            o.w = (v.w - mean)*inv*g4.w + b4.w;
            *(float4*)&out[(size_t)gr * EFq + (lane << 2)] = o;
        }
    }
}

// =====================================================================
extern "C" void kernel_launch(void* const* d_in, const int* in_sizes, int n_in,
                              void* d_out, int out_size) {
    const float* X         = (const float*)d_in[0];
    const float* mask      = (const float*)d_in[1];
    const float* atom_mask = (const float*)d_in[4];
    const float* W         = (const float*)d_in[5];
    const float* gamma_    = (const float*)d_in[6];
    const float* beta_     = (const float*)d_in[7];
    float* out = (float*)d_out;

    float* out_tail = (out_size >= Mrows * (EFq + 1)) ? (out + (size_t)Mrows * EFq)
                                                      : nullptr;

    prep_kernel<<<PREP_GRID, 256>>>(X, mask, W, out_tail);

    cudaFuncSetAttribute(fused_hmma_kernel,
                         cudaFuncAttributeMaxDynamicSharedMemorySize, SM_TOTAL);
    fused_hmma_kernel<<<Mrows/BM, 512, SM_TOTAL>>>(atom_mask, gamma_, beta_, out);
}

// round 14
// speedup vs baseline: 1.0877x; 1.0715x over previous
#include <cuda_runtime.h>
#include <cstdint>
#include <math.h>

#define Bq 2
#define Lq 1024
#define Aq 14
#define Kq 30
#define EFq 128
#define EDGE_INq 3152
#define Mrows (Bq*Lq*Kq)      // 61440
#define BM 128
#define NCHUNK 99             // padded K = 3168

typedef uint32_t u32;

// ---- scratch ----
__device__ int g_Eidx[Mrows];
__device__ __align__(16) float g_X2[Bq*Lq*Aq*3];
__device__ __align__(16) float g_Wfrag[NCHUNK*4096];  // fragment-ordered tf32 W

__constant__ float c_freq[8] = {
    1.0f, 0.31622776601683794f, 0.1f, 0.031622776601683794f,
    0.01f, 0.0031622776601683794f, 0.001f, 0.00031622776601683794f
};

__device__ __forceinline__ u32 f2tf32(float v) {
    u32 u; asm("cvt.rna.tf32.f32 %0, %1;" : "=r"(u) : "f"(v)); return u;
}
__device__ __forceinline__ float ex2f(float x) {
    float r; asm("ex2.approx.f32 %0, %1;" : "=f"(r) : "f"(x)); return r;
}
__device__ __forceinline__ u32 smem_u32(const void* p) {
    u32 a; asm("{ .reg .u64 t; cvta.to.shared.u64 t, %1; cvt.u32.u64 %0, t; }"
               : "=r"(a) : "l"(p));
    return a;
}
__device__ __forceinline__ void mma_tf32(float* d, const u32* a, u32 b0, u32 b1) {
    asm volatile("mma.sync.aligned.m16n8k8.row.col.f32.tf32.tf32.f32 "
        "{%0,%1,%2,%3}, {%4,%5,%6,%7}, {%8,%9}, {%0,%1,%2,%3};"
        : "+f"(d[0]), "+f"(d[1]), "+f"(d[2]), "+f"(d[3])
        : "r"(a[0]), "r"(a[1]), "r"(a[2]), "r"(a[3]), "r"(b0), "r"(b1));
}
#define LDS128(v, addr) asm volatile("ld.shared.v4.f32 {%0,%1,%2,%3}, [%4];" \
    : "=f"(v.x), "=f"(v.y), "=f"(v.z), "=f"(v.w) : "r"(addr))
#define STS128(addr, a0, a1, a2, a3) asm volatile( \
    "st.shared.v4.b32 [%0], {%1,%2,%3,%4};" \
    :: "r"(addr), "r"(a0), "r"(a1), "r"(a2), "r"(a3) : "memory")
#define MBARRIER_INIT(a,c) asm volatile( \
    "mbarrier.init.shared.b64 [%0], %1;" :: "r"(a), "r"(c) : "memory")
#define MBARRIER_EXPECT_TX(a,b) asm volatile( \
    "mbarrier.arrive.expect_tx.shared.b64 _, [%0], %1;" :: "r"(a), "r"(b) : "memory")
#define CP_BULK(dst, src, mbar) asm volatile( \
    "cp.async.bulk.shared::cta.global.mbarrier::complete_tx::bytes [%0], [%1], %2, [%3];" \
    :: "r"(dst), "l"(src), "r"(16384), "r"(mbar) : "memory")
#define MBAR_WAIT(a, ph) asm volatile("{\n\t.reg .pred P;\n\tWL_%=:\n\t" \
    "mbarrier.try_wait.parity.acquire.cta.shared::cta.b64 P, [%0], %1, 0x989680;\n\t" \
    "@!P bra WL_%=;\n\t}" :: "r"(a), "r"(ph) : "memory")

// =====================================================================
// Kernel 1 (merged prep): topk | prepW | buildX2
// =====================================================================
#define TOPK_BLOCKS  (Bq*Lq)                 // 2048
#define PREPW_BLOCKS ((NCHUNK*4096)/256)     // 1584
#define BX2_BLOCKS   8
#define PREP_GRID    (TOPK_BLOCKS + PREPW_BLOCKS + BX2_BLOCKS)

__global__ void prep_kernel(const float* __restrict__ X,
                            const float* __restrict__ mask,
                            const float* __restrict__ W,
                            float* __restrict__ out_tail) {
    __shared__ float Da[Lq];
    __shared__ float svals[8];
    __shared__ int   sidx[8];
    __shared__ float sDmax;

    int bid = blockIdx.x;
    int tid = threadIdx.x;

    if (bid >= TOPK_BLOCKS) {
        if (bid < TOPK_BLOCKS + PREPW_BLOCKS) {
            // ---- prepW: per chunk float idx e(0-1)|lane(2-6)|q(7-8)|s(9-10)|wn(11)
            int t = (bid - TOPK_BLOCKS) * 256 + tid;
            int e    = t & 3;
            int lane = (t >> 2) & 31;
            int q    = (t >> 7) & 3;
            int s    = (t >> 9) & 3;
            int wn   = (t >> 11) & 1;
            int k    = t >> 12;
            int nt   = 2*q + (e >> 1);
            int half = e & 1;
            int n = wn*64 + nt*8 + (lane >> 2);
            int c = k*32 + s*8 + (lane & 3) + half*4;
            float v = (c < EDGE_INq) ? W[(size_t)n * EDGE_INq + c] : 0.f;
            g_Wfrag[t] = __uint_as_float(f2tf32(v));
        } else {
            // ---- buildX2 ----
            int t = (bid - TOPK_BLOCKS - PREPW_BLOCKS) * 256 + tid;
            if (t < Bq * Lq) {
                const float* xr = X + (size_t)t * Aq * 3;
                float* o = g_X2 + (size_t)t * Aq * 3;
                #pragma unroll
                for (int a = 0; a < Aq*3; a++) o[a] = xr[a];
                float Nx = xr[0],  Ny = xr[1],  Nz = xr[2];
                float Cax= xr[3],  Cay= xr[4],  Caz= xr[5];
                float Cx = xr[6],  Cy = xr[7],  Cz = xr[8];
                float bx = Cax - Nx, by = Cay - Ny, bz = Caz - Nz;
                float cx = Cx - Cax, cy = Cy - Cay, cz = Cz - Caz;
                float ax = by*cz - bz*cy;
                float ay = bz*cx - bx*cz;
                float az = bx*cy - by*cx;
                o[12] = -0.58273431f*ax + 0.56802827f*bx - 0.54067466f*cx + Cax;
                o[13] = -0.58273431f*ay + 0.56802827f*by - 0.54067466f*cy + Cay;
                o[14] = -0.58273431f*az + 0.56802827f*bz - 0.54067466f*cz + Caz;
            }
        }
        return;
    }

    // ---- topk (unchanged) ----
    int bi  = bid;
    int b   = bi >> 10;
    int i   = bi & (Lq - 1);

    const float* Xb = X + (size_t)b * Lq * Aq * 3;
    float cx = Xb[(i*Aq+1)*3+0];
    float cy = Xb[(i*Aq+1)*3+1];
    float cz = Xb[(i*Aq+1)*3+2];
    float mi = mask[b*Lq + i];

    float lmax = 0.f;
    for (int j = tid; j < Lq; j += 256) {
        float dx = cx - Xb[(j*Aq+1)*3+0];
        float dy = cy - Xb[(j*Aq+1)*3+1];
        float dz = cz - Xb[(j*Aq+1)*3+2];
        float m2 = mi * mask[b*Lq + j];
        float D  = m2 * sqrtf(dx*dx + dy*dy + dz*dz + 1e-6f);
        Da[j] = D;
        lmax = fmaxf(lmax, D);
    }
    #pragma unroll
    for (int off = 16; off; off >>= 1)
        lmax = fmaxf(lmax, __shfl_xor_sync(0xffffffffu, lmax, off));
    if ((tid & 31) == 0) svals[tid >> 5] = lmax;
    __syncthreads();
    if (tid == 0) {
        float m = svals[0];
        for (int w = 1; w < 8; w++) m = fmaxf(m, svals[w]);
        sDmax = m;
    }
    __syncthreads();
    float Dmax = sDmax;
    for (int j = tid; j < Lq; j += 256) {
        float m2 = mi * mask[b*Lq + j];
        Da[j] += 2.f * (1.f - m2) * Dmax;
    }
    __syncthreads();

    for (int k = 0; k < Kq; k++) {
        float bv = 3.4e38f; int bj = 0x7fffffff;
        for (int j = tid; j < Lq; j += 256) {
            float v = Da[j];
            if (v < bv) { bv = v; bj = j; }
        }
        #pragma unroll
        for (int off = 16; off; off >>= 1) {
            float ov = __shfl_down_sync(0xffffffffu, bv, off);
            int   oj = __shfl_down_sync(0xffffffffu, bj, off);
            if (ov < bv || (ov == bv && oj < bj)) { bv = ov; bj = oj; }
        }
        if ((tid & 31) == 0) { svals[tid >> 5] = bv; sidx[tid >> 5] = bj; }
        __syncthreads();
        if (tid == 0) {
            for (int w = 1; w < 8; w++) {
                float v = svals[w]; int jj = sidx[w];
                if (v < bv || (v == bv && jj < bj)) { bv = v; bj = jj; }
            }
            int orow = bi * Kq + k;
            g_Eidx[orow] = bj;
            if (out_tail) out_tail[orow] = (float)bj;
            Da[bj] = 3.4e38f;
        }
        __syncthreads();
    }
}

// =====================================================================
// Kernel 2: fused featuregen + mma.sync tf32 + LayerNorm (R11 base)
// B tiles via single cp.async.bulk + per-buffer mbarrier (literal phases);
// B-wait moved AFTER produce so TMA latency hides under feature gen.
// =====================================================================
// byte offsets in dynamic smem
#define SM_SBF   0          // 3 * 16384 = 49152 (B triple buffer)
#define SM_SD    49152      // 2 bufs * 256 f = 2048
#define SM_SCO   51200      // 2048
#define SM_DPOS  53248      // 512
#define SM_IIDX  53760      // 512
#define SM_JIDX  54272      // 512
#define SM_AFR   54784      // 4 wm x 4 s x 2 mt x 512B = 16384
#define SM_MBAR  71168      // 3 mbarriers x 8B
#define SM_TOTAL 71232
#define ESTRIDE  132        // epilogue reuses bytes [0, 33792)

// ---------- stage sD(k+1) + issue bulk B(k+1) into buffer NB ----------
#define STAGE_NEXT(NB) do {                                                  \
    float D = 0.f, co = 0.f;                                                 \
    if (sp < 14) {                                                           \
        const float* xi = xi_b + sp*3;                                       \
        const float* xj = xj_b + sq*3;                                       \
        float dx = xi[0]-xj[0], dy = xi[1]-xj[1], dz = xi[2]-xj[2];          \
        D  = sqrtf(dx*dx + dy*dy + dz*dz + 1e-6f);                          \
        co = (1.f - ami_b[sp]) * (1.f - amj_b[sq]);                          \
    }                                                                        \
    sDf [st_wr ^ 256] = D;                                                   \
    sCof[st_wr ^ 256] = co;                                                  \
    st_wr ^= 256;                                                            \
    sq += 2; if (sq >= 14) { sq -= 14; sp += 1; }                            \
    if (tid == 0) {                                                          \
        MBARRIER_EXPECT_TX(mb + (NB)*8, 16384);                              \
        CP_BULK(sb + SM_SBF + (NB)*16384, wsrc_n, mb + (NB)*8);              \
    }                                                                        \
    wsrc_n += 1024;                                                          \
} while(0)

#define PRODUCE_RBF(SDB) do {                                                \
    _Pragma("unroll")                                                        \
    for (int sp2 = 0; sp2 < 2; sp2++) {                                      \
        float m0 = sp2 ? mu10 : mu00;                                        \
        float m1 = sp2 ? mu11 : mu01;                                        \
        _Pragma("unroll")                                                    \
        for (int mt = 0; mt < 2; mt++) {                                     \
            int ri = (SDB)*256 + sd_rd + (mt<<4);                            \
            float D0 = sDf[ri],     C0 = sCof[ri];                           \
            float D1 = sDf[ri + 8], C1 = sCof[ri + 8];                       \
            float t0 = D0 - m0, t1 = D1 - m0;                                \
            float t2 = D0 - m1, t3 = D1 - m1;                                \
            u32 v0 = f2tf32(C0 * ex2f(t0*t0*-0.9233248262f));                \
            u32 v1 = f2tf32(C1 * ex2f(t1*t1*-0.9233248262f));                \
            u32 v2 = f2tf32(C0 * ex2f(t2*t2*-0.9233248262f));                \
            u32 v3 = f2tf32(C1 * ex2f(t3*t3*-0.9233248262f));                \
            STS128(afr_st + (u32)(sp2*1024 + mt*512), v0, v1, v2, v3);       \
        }                                                                    \
    }                                                                        \
} while(0)

#define CONSUME(BB) do {                                                     \
    _Pragma("unroll")                                                        \
    for (int s = 0; s < 4; s++) {                                            \
        u32 afr[2][4];                                                       \
        _Pragma("unroll")                                                    \
        for (int mt = 0; mt < 2; mt++) {                                     \
            float4 av;                                                       \
            LDS128(av, abase + (u32)(((s<<1)+mt)<<9));                       \
            afr[mt][0] = __float_as_uint(av.x);                              \
            afr[mt][1] = __float_as_uint(av.y);                              \
            afr[mt][2] = __float_as_uint(av.z);                              \
            afr[mt][3] = __float_as_uint(av.w);                              \
        }                                                                    \
        _Pragma("unroll")                                                    \
        for (int q = 0; q < 4; q++) {                                        \
            float4 bv;                                                       \
            LDS128(bv, sbase + (u32)((BB)*16384 + (s<<11) + (q<<9)));        \
            u32 b0 = __float_as_uint(bv.x), b1 = __float_as_uint(bv.y);      \
            u32 b2 = __float_as_uint(bv.z), b3 = __float_as_uint(bv.w);      \
            _Pragma("unroll")                                                \
            for (int mt = 0; mt < 2; mt++) {                                 \
                mma_tf32(acc[mt][2*q],     afr[mt], b0, b1);                 \
                mma_tf32(acc[mt][2*q + 1], afr[mt], b2, b3);                 \
            }                                                                \
        }                                                                    \
    }                                                                        \
} while(0)

// WPH = literal mbarrier phase of buffer BB at this chunk
#define CHUNK_STD(SDB, BB, NB, WPH, HAS_NEXT) do {                           \
    if (HAS_NEXT) STAGE_NEXT(NB);                                            \
    __syncthreads();                                                         \
    PRODUCE_RBF(SDB);                                                        \
    __syncthreads();                                                         \
    MBAR_WAIT(mb + (BB)*8, WPH);                                             \
    CONSUME(BB);                                                             \
} while(0)

__global__ void __launch_bounds__(256, 2)
fused_hmma_kernel(const float* __restrict__ atom_mask,
                  const float* __restrict__ gamma_,
                  const float* __restrict__ beta_,
                  float* __restrict__ out) {
    extern __shared__ char smc[];
    u32 sb = smem_u32(smc);
    float* sE    = (float*)(smc);               // epilogue reuse
    float* sDf   = (float*)(smc + SM_SD);
    float* sCof  = (float*)(smc + SM_SCO);
    float* dposS = (float*)(smc + SM_DPOS);
    int*   iidx  = (int*)(smc + SM_IIDX);
    int*   jidx  = (int*)(smc + SM_JIDX);
    u32    mb    = sb + SM_MBAR;

    int tid  = threadIdx.x;
    int wid  = tid >> 5, lane = tid & 31;
    int wm   = wid & 3, wn = wid >> 2;
    int lq   = lane >> 2;    // 0..7
    int lr   = lane & 3;     // 0..3
    int row0 = blockIdx.x * BM;

    if (tid < BM) {
        int gr  = row0 + tid;
        int b   = gr / (Lq * Kq);
        int rem = gr - b * (Lq * Kq);
        int i   = rem / Kq;
        int j   = g_Eidx[gr];
        iidx[tid] = b * Lq + i;
        jidx[tid] = b * Lq + j;
        dposS[tid] = (float)(j - i);
    }
    if (tid == 0) {
        MBARRIER_INIT(mb + 0,  1);
        MBARRIER_INIT(mb + 8,  1);
        MBARRIER_INIT(mb + 16, 1);
    }
    __syncthreads();

    // ---- hoisted per-thread staging state ----
    int srow = tid & 127;
    int sl   = tid >> 7;
    const float* xi_b  = g_X2 + iidx[srow]*42;
    const float* xj_b  = g_X2 + jidx[srow]*42;
    const float* ami_b = atom_mask + iidx[srow]*14;
    const float* amj_b = atom_mask + jidx[srow]*14;
    int sp = 0, sq = 1 + sl;
    int st_wr = (sl << 7) + srow;

    // ---- stage chunk 0 into sD buf 0 (P = -1+sl) ----
    {
        float D = 0.f, co = 0.f;
        if (sl == 1) {
            float dx = xi_b[0]-xj_b[0], dy = xi_b[1]-xj_b[1], dz = xi_b[2]-xj_b[2];
            D  = sqrtf(dx*dx + dy*dy + dz*dz + 1e-6f);
            co = (1.f - ami_b[0]) * (1.f - amj_b[0]);
        }
        sDf [st_wr] = D;
        sCof[st_wr] = co;
        st_wr ^= 256;
    }
    st_wr ^= 256;        // STAGE_NEXT pre-toggles; leave at buf0 state

    // ---- B(0) bulk issue (buf0, phase 0) ----
    const float4* wsrc_n = (const float4*)g_Wfrag;
    if (tid == 0) {
        MBARRIER_EXPECT_TX(mb + 0, 16384);
        CP_BULK(sb + SM_SBF, wsrc_n, mb + 0);
    }
    wsrc_n += 1024;      // -> chunk 1

    // ---- hoisted producer/consumer bases ----
    int sd_rd   = (wn << 7) + (wm << 5) + lq;
    u32 afr_st  = sb + SM_AFR + (u32)((wm << 12) + (wn << 11) + (lane << 4));
    u32 abase   = sb + SM_AFR + (u32)((wm << 12) + (lane << 4));
    u32 sbase   = sb + SM_SBF + (u32)((wn << 13) + (lane << 4));
    float mu00 = (float)lr * 1.3333333333f;
    float mu01 = mu00 + 5.3333333333f;
    float mu10 = (float)(8 + lr) * 1.3333333333f;
    float mu11 = mu10 + 5.3333333333f;

    float acc[2][8][4];
    #pragma unroll
    for (int mt = 0; mt < 2; mt++)
        #pragma unroll
        for (int nt = 0; nt < 8; nt++)
            #pragma unroll
            for (int c = 0; c < 4; c++) acc[mt][nt][c] = 0.f;

    // ================= chunk 0 (posenc special) =================
    {
        STAGE_NEXT(1);                       // sD buf1, B(1) -> buf1 (ph0)
        __syncthreads();
        if (wn == 0) {
            #pragma unroll
            for (int sp2 = 0; sp2 < 2; sp2++) {
                #pragma unroll
                for (int mt = 0; mt < 2; mt++) {
                    int r0 = (wm << 5) + (mt << 4) + lq;
                    float d0 = dposS[r0], d1 = dposS[r0 + 8];
                    float s0a, c0a, s1a, c1a, s0b, c0b, s1b, c1b;
                    sincosf(d0 * c_freq[lr],     &s0a, &c0a);
                    sincosf(d1 * c_freq[lr],     &s1a, &c1a);
                    sincosf(d0 * c_freq[lr + 4], &s0b, &c0b);
                    sincosf(d1 * c_freq[lr + 4], &s1b, &c1b);
                    u32 v0, v1, v2, v3;
                    if (sp2 == 0) {
                        v0 = f2tf32(c0a); v1 = f2tf32(c1a);
                        v2 = f2tf32(c0b); v3 = f2tf32(c1b);
                    } else {
                        v0 = f2tf32(s0a); v1 = f2tf32(s1a);
                        v2 = f2tf32(s0b); v3 = f2tf32(s1b);
                    }
                    STS128(afr_st + (u32)(sp2*1024 + mt*512), v0, v1, v2, v3);
                }
            }
        } else {
            PRODUCE_RBF(0);
        }
        __syncthreads();
        MBAR_WAIT(mb + 0, 0);                // B(0) buf0 phase 0
        CONSUME(0);
    }

    // ================= chunks 1..96 : 16 x 6 unrolled =================
    // buffer t=floor(k/3); phase = t&1  (literals per slot)
    #pragma unroll 1
    for (int kb = 0; kb < 16; kb++) {
        CHUNK_STD(1, 1, 2, 0, 1);   // k = 6kb+1
        CHUNK_STD(0, 2, 0, 0, 1);   // k = 6kb+2
        CHUNK_STD(1, 0, 1, 1, 1);   // k = 6kb+3
        CHUNK_STD(0, 1, 2, 1, 1);   // k = 6kb+4
        CHUNK_STD(1, 2, 0, 1, 1);   // k = 6kb+5
        CHUNK_STD(0, 0, 1, 0, 1);   // k = 6kb+6
    }
    // ================= chunks 97, 98 =================
    CHUNK_STD(1, 1, 2, 0, 1);       // k = 97 (stages 98; sp<14 guards)
    CHUNK_STD(0, 2, 0, 0, 0);       // k = 98 (no next)

    // ================= epilogue: 2 halves of 64 rows =================
    float4 g4 = *(const float4*)&gamma_[lane << 2];
    float4 b4 = *(const float4*)&beta_ [lane << 2];

    #pragma unroll
    for (int h = 0; h < 2; h++) {
        __syncthreads();
        if ((wm >> 1) == h) {
            #pragma unroll
            for (int mt = 0; mt < 2; mt++) {
                int rl = (wm << 5) + (mt << 4) + lq - (h << 6);
                #pragma unroll
                for (int nt = 0; nt < 8; nt++) {
                    int col = (wn << 6) + (nt << 3) + (lr << 1);
                    *(float2*)&sE[ rl      * ESTRIDE + col] =
                        make_float2(acc[mt][nt][0], acc[mt][nt][1]);
                    *(float2*)&sE[(rl + 8) * ESTRIDE + col] =
                        make_float2(acc[mt][nt][2], acc[mt][nt][3]);
                }
            }
        }
        __syncthreads();
        #pragma unroll
        for (int rr = 0; rr < 8; rr++) {
            int rl = (wid << 3) + rr;
            float4 v = *(const float4*)&sE[rl * ESTRIDE + (lane << 2)];
            float s  = v.x + v.y + v.z + v.w;
            float sq2 = v.x*v.x + v.y*v.y + v.z*v.z + v.w*v.w;
            #pragma unroll
            for (int off = 16; off; off >>= 1) {
                s   += __shfl_xor_sync(0xffffffffu, s,   off);
                sq2 += __shfl_xor_sync(0xffffffffu, sq2, off);
            }
            float mean = s * (1.f/128.f);
            float var  = sq2 * (1.f/128.f) - mean * mean;
            float inv  = rsqrtf(var + 1e-5f);
            int gr = row0 + (h << 6) + rl;
            float4 o;
            o.x = (v.x - mean)*inv*g4.x + b4.x;
            o.y = (v.y - mean)*inv*g4.y + b4.y;
            o.z = (v.z - mean)*inv*g4.z + b4.z;
            o.w = (v.w - mean)*inv*g4.w + b4.w;
            *(float4*)&out[(size_t)gr * EFq + (lane << 2)] = o;
        }
    }
}

// =====================================================================
extern "C" void kernel_launch(void* const* d_in, const int* in_sizes, int n_in,
                              void* d_out, int out_size) {
    const float* X         = (const float*)d_in[0];
    const float* mask      = (const float*)d_in[1];
    const float* atom_mask = (const float*)d_in[4];
    const float* W         = (const float*)d_in[5];
    const float* gamma_    = (const float*)d_in[6];
    const float* beta_     = (const float*)d_in[7];
    float* out = (float*)d_out;

    float* out_tail = (out_size >= Mrows * (EFq + 1)) ? (out + (size_t)Mrows * EFq)
                                                      : nullptr;

    prep_kernel<<<PREP_GRID, 256>>>(X, mask, W, out_tail);

    cudaFuncSetAttribute(fused_hmma_kernel,
                         cudaFuncAttributeMaxDynamicSharedMemorySize, SM_TOTAL);
    fused_hmma_kernel<<<Mrows/BM, 256, SM_TOTAL>>>(atom_mask, gamma_, beta_, out);
}